// round 6
// baseline (speedup 1.0000x reference)
#include <cuda_runtime.h>
#include <math.h>
#include <stdint.h>

#define D_MODEL 1024
#define NUM_HEADS 16
#define DK 64
#define BATCH 2
#define SEQ 2048
#define M_TOTAL (BATCH * SEQ)  // 4096

// GEMM smem geometry
#define A_ROW_STRIDE 20
#define A_STAGE_WORDS (128 * A_ROW_STRIDE)
#define B0_STAGE_WORDS (16 * 136)
#define B1_STAGE_WORDS (128 * A_ROW_STRIDE)
#define NSTAGE 3

// flash smem geometry (all strides 72 words: conflict-free patterns)
#define FRS 72
#define KV_WORDS (64 * FRS)            // 4608 words per matrix
#define P_WARP_WORDS (32 * FRS)        // 2304 words per warp

__device__ float g_q[BATCH * NUM_HEADS * SEQ * DK];
__device__ float g_k[BATCH * NUM_HEADS * SEQ * DK];
__device__ float g_v[BATCH * NUM_HEADS * SEQ * DK];
__device__ float g_cat[M_TOTAL * D_MODEL];

__device__ __forceinline__ uint32_t f2tf(float f) {
    uint32_t u;
    asm("cvt.rna.tf32.f32 %0, %1;" : "=r"(u) : "f"(f));
    return u;
}

__device__ __forceinline__ void mma_tf32(float* c, const uint32_t* a, const uint32_t* b) {
    asm volatile(
        "mma.sync.aligned.m16n8k8.row.col.f32.tf32.tf32.f32 "
        "{%0,%1,%2,%3}, {%4,%5,%6,%7}, {%8,%9}, {%0,%1,%2,%3};"
        : "+f"(c[0]), "+f"(c[1]), "+f"(c[2]), "+f"(c[3])
        : "r"(a[0]), "r"(a[1]), "r"(a[2]), "r"(a[3]), "r"(b[0]), "r"(b[1]));
}
__device__ __forceinline__ void mma_tf32_v(float* c, const uint32_t* a, uint32_t b0, uint32_t b1) {
    asm volatile(
        "mma.sync.aligned.m16n8k8.row.col.f32.tf32.tf32.f32 "
        "{%0,%1,%2,%3}, {%4,%5,%6,%7}, {%8,%9}, {%0,%1,%2,%3};"
        : "+f"(c[0]), "+f"(c[1]), "+f"(c[2]), "+f"(c[3])
        : "r"(a[0]), "r"(a[1]), "r"(a[2]), "r"(a[3]), "r"(b0), "r"(b1));
}

__device__ __forceinline__ void cpa16(uint32_t* smem_dst, const float* gsrc) {
    uint32_t s = (uint32_t)__cvta_generic_to_shared(smem_dst);
    asm volatile("cp.async.cg.shared.global [%0], [%1], 16;" :: "r"(s), "l"(gsrc));
}
__device__ __forceinline__ void cpa_commit() {
    asm volatile("cp.async.commit_group;");
}
template <int N>
__device__ __forceinline__ void cpa_wait() {
    asm volatile("cp.async.wait_group %0;" :: "n"(N));
}

// =====================================================================
// TF32 GEMM (R5, known-good): cp.async 3-stage, HW tf32 truncation.
// MODE 1 (out): out[m,n] = X @ Wo[n,:]^T + bo
// =====================================================================
template <int MODE>
__global__ __launch_bounds__(256, 2) void gemm_v2_kernel(
    const float* __restrict__ X, const float* __restrict__ W,
    const float* __restrict__ bias, float* __restrict__ out)
{
    extern __shared__ uint32_t sg[];
    uint32_t* smA = sg;
    uint32_t* smB = sg + NSTAGE * A_STAGE_WORDS;
    const int BSTW = (MODE == 0) ? B0_STAGE_WORDS : B1_STAGE_WORDS;

    const int t    = threadIdx.x;
    const int n0   = blockIdx.x * 128;
    const int m0   = blockIdx.y * 128;
    const int warp = t >> 5;
    const int lane = t & 31;
    const int gid  = lane >> 2;
    const int tig  = lane & 3;
    const int wm   = (warp & 1) * 64;
    const int wn   = (warp >> 1) * 32;

    const int am[2] = { (t + 0) >> 2, (t + 256) >> 2 };
    const int ak4   = (t & 3) << 2;

    float acc[4][4][4];
#pragma unroll
    for (int i = 0; i < 4; i++)
#pragma unroll
        for (int j = 0; j < 4; j++)
#pragma unroll
            for (int k = 0; k < 4; k++) acc[i][j][k] = 0.f;

    auto issue = [&](int stage, int kc) {
        uint32_t* As_ = smA + stage * A_STAGE_WORDS;
        uint32_t* Bs_ = smB + stage * BSTW;
#pragma unroll
        for (int rep = 0; rep < 2; rep++) {
            int m = am[rep];
            cpa16(As_ + m * A_ROW_STRIDE + ak4,
                  X + (size_t)(m0 + m) * D_MODEL + kc * 16 + ak4);
        }
#pragma unroll
        for (int rep = 0; rep < 2; rep++) {
            int f = t + rep * 256;
            if (MODE == 0) {
                int k = f >> 5, n4 = (f & 31) << 2;
                int bn = n0 + n4;
                int ck = ((k >> 2) & 3) << 2;
                cpa16(Bs_ + k * 136 + (n4 ^ ck),
                      W + (size_t)(bn >> 6) * (D_MODEL * DK)
                        + (size_t)(kc * 16 + k) * DK + (bn & 63));
            } else {
                int n = f >> 2, k4 = (f & 3) << 2;
                cpa16(Bs_ + n * A_ROW_STRIDE + k4,
                      W + (size_t)(n0 + n) * D_MODEL + kc * 16 + k4);
            }
        }
    };

    auto compute = [&](int stage) {
        uint32_t* As_ = smA + stage * A_STAGE_WORDS;
        uint32_t* Bs_ = smB + stage * BSTW;
#pragma unroll
        for (int ks = 0; ks < 2; ks++) {
            const int kb = ks * 8;
            uint32_t af[4][4];
#pragma unroll
            for (int mt = 0; mt < 4; mt++) {
                const int r = (wm + mt * 16 + gid) * A_ROW_STRIDE;
                af[mt][0] = As_[r + kb + tig];
                af[mt][1] = As_[r + 8 * A_ROW_STRIDE + kb + tig];
                af[mt][2] = As_[r + kb + tig + 4];
                af[mt][3] = As_[r + 8 * A_ROW_STRIDE + kb + tig + 4];
            }
            uint32_t bf[4][2];
#pragma unroll
            for (int nt = 0; nt < 4; nt++) {
                const int ncol = wn + nt * 8 + gid;
                if (MODE == 0) {
                    const int x0 = ks ? 8 : 0;
                    const int x1 = ks ? 12 : 4;
                    bf[nt][0] = Bs_[(kb + tig) * 136 + (ncol ^ x0)];
                    bf[nt][1] = Bs_[(kb + tig + 4) * 136 + (ncol ^ x1)];
                } else {
                    bf[nt][0] = Bs_[ncol * A_ROW_STRIDE + kb + tig];
                    bf[nt][1] = Bs_[ncol * A_ROW_STRIDE + kb + tig + 4];
                }
            }
#pragma unroll
            for (int mt = 0; mt < 4; mt++)
#pragma unroll
                for (int nt = 0; nt < 4; nt++) mma_tf32(acc[mt][nt], af[mt], bf[nt]);
        }
    };

    issue(0, 0); cpa_commit();
    issue(1, 1); cpa_commit();
    int stage = 0;
    for (int kc = 0; kc < 64; kc++) {
        cpa_wait<1>();
        __syncthreads();
        compute(stage);
        __syncthreads();
        if (kc + 2 < 64) issue((kc + 2) % NSTAGE, kc + 2);
        cpa_commit();
        stage = (stage + 1) % NSTAGE;
    }

#pragma unroll
    for (int mt = 0; mt < 4; mt++) {
#pragma unroll
        for (int nt = 0; nt < 4; nt++) {
            const int r0 = m0 + wm + mt * 16 + gid;
            const int r1 = r0 + 8;
            const int c  = n0 + wn + nt * 8 + tig * 2;
            const float bv0 = bias[c], bv1 = bias[c + 1];
            float2 v0 = make_float2(acc[mt][nt][0] + bv0, acc[mt][nt][1] + bv1);
            float2 v1 = make_float2(acc[mt][nt][2] + bv0, acc[mt][nt][3] + bv1);
            if (MODE == 0) {
                const int h = c >> 6, kd = c & 63;
                const int b0_ = r0 >> 11, s0 = r0 & 2047;
                const int b1_ = r1 >> 11, s1 = r1 & 2047;
                *(float2*)(out + (((size_t)b0_ * NUM_HEADS + h) * SEQ + s0) * DK + kd) = v0;
                *(float2*)(out + (((size_t)b1_ * NUM_HEADS + h) * SEQ + s1) * DK + kd) = v1;
            } else {
                *(float2*)(out + (size_t)r0 * D_MODEL + c) = v0;
                *(float2*)(out + (size_t)r1 * D_MODEL + c) = v1;
            }
        }
    }
}

// proj wrapper (R5, known-good): grid.z selects Q/K/V
struct ProjArgs {
    const float* X[3];
    const float* W[3];
    const float* bias[3];
    float* out[3];
};

__global__ __launch_bounds__(256, 2) void proj_gemm3_v2_kernel(ProjArgs args)
{
    extern __shared__ uint32_t sg[];
    const int z = blockIdx.z;
    const float* X    = args.X[z];
    const float* W    = args.W[z];
    const float* bias = args.bias[z];
    float* out        = args.out[z];

    uint32_t* smA = sg;
    uint32_t* smB = sg + NSTAGE * A_STAGE_WORDS;

    const int t    = threadIdx.x;
    const int n0   = blockIdx.x * 128;
    const int m0   = blockIdx.y * 128;
    const int warp = t >> 5;
    const int lane = t & 31;
    const int gid  = lane >> 2;
    const int tig  = lane & 3;
    const int wm   = (warp & 1) * 64;
    const int wn   = (warp >> 1) * 32;

    const int am[2] = { (t + 0) >> 2, (t + 256) >> 2 };
    const int ak4   = (t & 3) << 2;

    float acc[4][4][4];
#pragma unroll
    for (int i = 0; i < 4; i++)
#pragma unroll
        for (int j = 0; j < 4; j++)
#pragma unroll
            for (int k = 0; k < 4; k++) acc[i][j][k] = 0.f;

    auto issue = [&](int stage, int kc) {
        uint32_t* As_ = smA + stage * A_STAGE_WORDS;
        uint32_t* Bs_ = smB + stage * B0_STAGE_WORDS;
#pragma unroll
        for (int rep = 0; rep < 2; rep++) {
            int m = am[rep];
            cpa16(As_ + m * A_ROW_STRIDE + ak4,
                  X + (size_t)(m0 + m) * D_MODEL + kc * 16 + ak4);
        }
#pragma unroll
        for (int rep = 0; rep < 2; rep++) {
            int f = t + rep * 256;
            int k = f >> 5, n4 = (f & 31) << 2;
            int bn = n0 + n4;
            int ck = ((k >> 2) & 3) << 2;
            cpa16(Bs_ + k * 136 + (n4 ^ ck),
                  W + (size_t)(bn >> 6) * (D_MODEL * DK)
                    + (size_t)(kc * 16 + k) * DK + (bn & 63));
        }
    };

    auto compute = [&](int stage) {
        uint32_t* As_ = smA + stage * A_STAGE_WORDS;
        uint32_t* Bs_ = smB + stage * B0_STAGE_WORDS;
#pragma unroll
        for (int ks = 0; ks < 2; ks++) {
            const int kb = ks * 8;
            const int x0 = ks ? 8 : 0;
            const int x1 = ks ? 12 : 4;
            uint32_t af[4][4];
#pragma unroll
            for (int mt = 0; mt < 4; mt++) {
                const int r = (wm + mt * 16 + gid) * A_ROW_STRIDE;
                af[mt][0] = As_[r + kb + tig];
                af[mt][1] = As_[r + 8 * A_ROW_STRIDE + kb + tig];
                af[mt][2] = As_[r + kb + tig + 4];
                af[mt][3] = As_[r + 8 * A_ROW_STRIDE + kb + tig + 4];
            }
            uint32_t bf[4][2];
#pragma unroll
            for (int nt = 0; nt < 4; nt++) {
                const int ncol = wn + nt * 8 + gid;
                bf[nt][0] = Bs_[(kb + tig) * 136 + (ncol ^ x0)];
                bf[nt][1] = Bs_[(kb + tig + 4) * 136 + (ncol ^ x1)];
            }
#pragma unroll
            for (int mt = 0; mt < 4; mt++)
#pragma unroll
                for (int nt = 0; nt < 4; nt++) mma_tf32(acc[mt][nt], af[mt], bf[nt]);
        }
    };

    issue(0, 0); cpa_commit();
    issue(1, 1); cpa_commit();
    int stage = 0;
    for (int kc = 0; kc < 64; kc++) {
        cpa_wait<1>();
        __syncthreads();
        compute(stage);
        __syncthreads();
        if (kc + 2 < 64) issue((kc + 2) % NSTAGE, kc + 2);
        cpa_commit();
        stage = (stage + 1) % NSTAGE;
    }

#pragma unroll
    for (int mt = 0; mt < 4; mt++) {
#pragma unroll
        for (int nt = 0; nt < 4; nt++) {
            const int r0 = m0 + wm + mt * 16 + gid;
            const int r1 = r0 + 8;
            const int c  = n0 + wn + nt * 8 + tig * 2;
            const float bv0 = bias[c], bv1 = bias[c + 1];
            float2 v0 = make_float2(acc[mt][nt][0] + bv0, acc[mt][nt][1] + bv1);
            float2 v1 = make_float2(acc[mt][nt][2] + bv0, acc[mt][nt][3] + bv1);
            const int h = c >> 6, kd = c & 63;
            const int b0_ = r0 >> 11, s0 = r0 & 2047;
            const int b1_ = r1 >> 11, s1 = r1 & 2047;
            *(float2*)(out + (((size_t)b0_ * NUM_HEADS + h) * SEQ + s0) * DK + kd) = v0;
            *(float2*)(out + (((size_t)b1_ * NUM_HEADS + h) * SEQ + s1) * DK + kd) = v1;
        }
    }
}

// =====================================================================
// Flash attention v5: 128 threads / 4 warps, 32 q-rows per warp
// (two m16 tiles) -> every K/V fragment feeds 2 mmas.
// K,V smem: pair-permuted cols (d -> (d&3)*2+(d>>2) within 8-block),
// stride 72 -> K fragments via conflict-free LDS.64; V scalar loads
// conflict-free. P per-warp, stride 72, conflict-free.
// =====================================================================
__global__ __launch_bounds__(128, 2) void flash_v5_kernel()
{
    extern __shared__ uint32_t smu[];
    uint32_t* Ks = smu;                  // [64][FRS] permuted
    uint32_t* Vs = smu + KV_WORDS;       // [64][FRS] permuted
    uint32_t* Ps = smu + 2 * KV_WORDS;   // 4 warps * [32][FRS]

    const int t    = threadIdx.x;
    const int warp = t >> 5;
    const int lane = t & 31;
    const int gid  = lane >> 2;
    const int tig  = lane & 3;
    const int pgid = (gid & 3) * 2 + (gid >> 2);   // permuted col of gid
    const int q0   = blockIdx.x * 128;
    const int bh   = blockIdx.y;

    const float* qb = g_q + (size_t)bh * SEQ * DK;
    const float* kb = g_k + (size_t)bh * SEQ * DK;
    const float* vb = g_v + (size_t)bh * SEQ * DK;

    // Q fragments for 2 row-tiles (rows rbase+gid, +8, +16, +24), scale 1/8
    const int rbase = q0 + warp * 32;
    uint32_t qf0[8][4], qf1[8][4];
#pragma unroll
    for (int kk = 0; kk < 8; kk++) {
        qf0[kk][0] = f2tf(qb[(size_t)(rbase + gid)      * DK + kk * 8 + tig]     * 0.125f);
        qf0[kk][1] = f2tf(qb[(size_t)(rbase + gid + 8)  * DK + kk * 8 + tig]     * 0.125f);
        qf0[kk][2] = f2tf(qb[(size_t)(rbase + gid)      * DK + kk * 8 + tig + 4] * 0.125f);
        qf0[kk][3] = f2tf(qb[(size_t)(rbase + gid + 8)  * DK + kk * 8 + tig + 4] * 0.125f);
        qf1[kk][0] = f2tf(qb[(size_t)(rbase + gid + 16) * DK + kk * 8 + tig]     * 0.125f);
        qf1[kk][1] = f2tf(qb[(size_t)(rbase + gid + 24) * DK + kk * 8 + tig]     * 0.125f);
        qf1[kk][2] = f2tf(qb[(size_t)(rbase + gid + 16) * DK + kk * 8 + tig + 4] * 0.125f);
        qf1[kk][3] = f2tf(qb[(size_t)(rbase + gid + 24) * DK + kk * 8 + tig + 4] * 0.125f);
    }

    uint32_t* Pw = Ps + warp * P_WARP_WORDS;

    float mm[4], ll[4];
#pragma unroll
    for (int i = 0; i < 4; i++) { mm[i] = -INFINITY; ll[i] = 0.f; }
    float o[2][8][4];
#pragma unroll
    for (int tl = 0; tl < 2; tl++)
#pragma unroll
        for (int j = 0; j < 8; j++)
#pragma unroll
            for (int k = 0; k < 4; k++) o[tl][j][k] = 0.f;

    const int lrow  = t >> 1;             // loader row 0..63
    const int lcol0 = (t & 1) * 32;       // loader col block

    for (int s0 = 0; s0 < SEQ; s0 += 64) {
        __syncthreads();
        // ---- load K,V tile, convert, pair-permute, STS.128 ----
        {
            const float* krow = kb + (size_t)(s0 + lrow) * DK + lcol0;
            const float* vrow = vb + (size_t)(s0 + lrow) * DK + lcol0;
            uint32_t* kdst = Ks + lrow * FRS + lcol0;
            uint32_t* vdst = Vs + lrow * FRS + lcol0;
#pragma unroll
            for (int cb = 0; cb < 4; cb++) {
                float4 a = *(const float4*)(krow + cb * 8);
                float4 b = *(const float4*)(krow + cb * 8 + 4);
                uint4 w0 = make_uint4(f2tf(a.x), f2tf(b.x), f2tf(a.y), f2tf(b.y));
                uint4 w1 = make_uint4(f2tf(a.z), f2tf(b.z), f2tf(a.w), f2tf(b.w));
                *(uint4*)(kdst + cb * 8)     = w0;
                *(uint4*)(kdst + cb * 8 + 4) = w1;
                float4 c = *(const float4*)(vrow + cb * 8);
                float4 d = *(const float4*)(vrow + cb * 8 + 4);
                uint4 x0 = make_uint4(f2tf(c.x), f2tf(d.x), f2tf(c.y), f2tf(d.y));
                uint4 x1 = make_uint4(f2tf(c.z), f2tf(d.z), f2tf(c.w), f2tf(d.w));
                *(uint4*)(vdst + cb * 8)     = x0;
                *(uint4*)(vdst + cb * 8 + 4) = x1;
            }
        }
        __syncthreads();

        // ---- S = Q K^T (both row-tiles share K fragments) ----
        float sacc[2][8][4];
#pragma unroll
        for (int tl = 0; tl < 2; tl++)
#pragma unroll
            for (int j = 0; j < 8; j++)
#pragma unroll
                for (int k = 0; k < 4; k++) sacc[tl][j][k] = 0.f;
#pragma unroll
        for (int kk = 0; kk < 8; kk++) {
#pragma unroll
            for (int j = 0; j < 8; j++) {
                uint2 b = *(const uint2*)&Ks[(j * 8 + gid) * FRS + kk * 8 + 2 * tig];
                mma_tf32_v(sacc[0][j], qf0[kk], b.x, b.y);
                mma_tf32_v(sacc[1][j], qf1[kk], b.x, b.y);
            }
        }

        // ---- online softmax per row-tile ----
#pragma unroll
        for (int tl = 0; tl < 2; tl++) {
            float t0 = -INFINITY, t1 = -INFINITY;
#pragma unroll
            for (int j = 0; j < 8; j++) {
                t0 = fmaxf(t0, fmaxf(sacc[tl][j][0], sacc[tl][j][1]));
                t1 = fmaxf(t1, fmaxf(sacc[tl][j][2], sacc[tl][j][3]));
            }
            t0 = fmaxf(t0, __shfl_xor_sync(0xffffffffu, t0, 1));
            t0 = fmaxf(t0, __shfl_xor_sync(0xffffffffu, t0, 2));
            t1 = fmaxf(t1, __shfl_xor_sync(0xffffffffu, t1, 1));
            t1 = fmaxf(t1, __shfl_xor_sync(0xffffffffu, t1, 2));

            float nm0 = fmaxf(mm[2 * tl], t0), nm1 = fmaxf(mm[2 * tl + 1], t1);
            float a0 = __expf(mm[2 * tl] - nm0), a1 = __expf(mm[2 * tl + 1] - nm1);
            mm[2 * tl] = nm0; mm[2 * tl + 1] = nm1;

            float p0 = 0.f, p1 = 0.f;
            uint32_t* Pt = Pw + (tl * 16) * FRS;
#pragma unroll
            for (int j = 0; j < 8; j++) {
                float e0 = __expf(sacc[tl][j][0] - nm0);
                float e1 = __expf(sacc[tl][j][1] - nm0);
                float e2 = __expf(sacc[tl][j][2] - nm1);
                float e3 = __expf(sacc[tl][j][3] - nm1);
                p0 += e0 + e1;
                p1 += e2 + e3;
                *(uint2*)&Pt[gid * FRS + j * 8 + 2 * tig]       = make_uint2(f2tf(e0), f2tf(e1));
                *(uint2*)&Pt[(gid + 8) * FRS + j * 8 + 2 * tig] = make_uint2(f2tf(e2), f2tf(e3));
            }
            p0 += __shfl_xor_sync(0xffffffffu, p0, 1);
            p0 += __shfl_xor_sync(0xffffffffu, p0, 2);
            p1 += __shfl_xor_sync(0xffffffffu, p1, 1);
            p1 += __shfl_xor_sync(0xffffffffu, p1, 2);
            ll[2 * tl]     = ll[2 * tl] * a0 + p0;
            ll[2 * tl + 1] = ll[2 * tl + 1] * a1 + p1;

#pragma unroll
            for (int j = 0; j < 8; j++) {
                o[tl][j][0] *= a0; o[tl][j][1] *= a0;
                o[tl][j][2] *= a1; o[tl][j][3] *= a1;
            }
        }
        __syncwarp();

        // ---- O += P V (both row-tiles share V fragments) ----
        // NOTE: P stored in NORMAL column order (j*8 + 2tig), so A-fragment
        // loads use normal cols; V stored permuted -> col pgid.
#pragma unroll
        for (int kk = 0; kk < 8; kk++) {
            uint32_t af0[4], af1[4];
            af0[0] = Pw[gid * FRS + kk * 8 + tig];
            af0[1] = Pw[(gid + 8) * FRS + kk * 8 + tig];
            af0[2] = Pw[gid * FRS + kk * 8 + tig + 4];
            af0[3] = Pw[(gid + 8) * FRS + kk * 8 + tig + 4];
            af1[0] = Pw[(16 + gid) * FRS + kk * 8 + tig];
            af1[1] = Pw[(24 + gid) * FRS + kk * 8 + tig];
            af1[2] = Pw[(16 + gid) * FRS + kk * 8 + tig + 4];
            af1[3] = Pw[(24 + gid) * FRS + kk * 8 + tig + 4];
#pragma unroll
            for (int j = 0; j < 8; j++) {
                uint32_t bf0 = Vs[(kk * 8 + tig) * FRS + j * 8 + pgid];
                uint32_t bf1 = Vs[(kk * 8 + tig + 4) * FRS + j * 8 + pgid];
                mma_tf32_v(o[0][j], af0, bf0, bf1);
                mma_tf32_v(o[1][j], af1, bf0, bf1);
            }
        }
        __syncwarp();
    }

    // ---- epilogue ----
    const int b_ = bh >> 4, h = bh & 15;
#pragma unroll
    for (int tl = 0; tl < 2; tl++) {
        const float i0 = 1.f / ll[2 * tl], i1 = 1.f / ll[2 * tl + 1];
        const int rA = rbase + tl * 16 + gid;
        const int rB = rA + 8;
        float* rowA = g_cat + (size_t)(b_ * SEQ + rA) * D_MODEL + h * DK;
        float* rowB = g_cat + (size_t)(b_ * SEQ + rB) * D_MODEL + h * DK;
#pragma unroll
        for (int j = 0; j < 8; j++) {
            *(float2*)(rowA + j * 8 + tig * 2) = make_float2(o[tl][j][0] * i0, o[tl][j][1] * i0);
            *(float2*)(rowB + j * 8 + tig * 2) = make_float2(o[tl][j][2] * i1, o[tl][j][3] * i1);
        }
    }
}

extern "C" void kernel_launch(void* const* d_in, const int* in_sizes, int n_in,
                              void* d_out, int out_size)
{
    const float* Q  = (const float*)d_in[0];
    const float* K  = (const float*)d_in[1];
    const float* V  = (const float*)d_in[2];
    const float* Wq = (const float*)d_in[3];
    const float* bq = (const float*)d_in[4];
    const float* Wk = (const float*)d_in[5];
    const float* bk = (const float*)d_in[6];
    const float* Wv = (const float*)d_in[7];
    const float* bv = (const float*)d_in[8];
    const float* Wo = (const float*)d_in[9];
    const float* bo = (const float*)d_in[10];
    float* out = (float*)d_out;

    float *gq, *gk, *gv, *gcat;
    cudaGetSymbolAddress((void**)&gq, g_q);
    cudaGetSymbolAddress((void**)&gk, g_k);
    cudaGetSymbolAddress((void**)&gv, g_v);
    cudaGetSymbolAddress((void**)&gcat, g_cat);

    const int proj_smem  = (NSTAGE * A_STAGE_WORDS + NSTAGE * B0_STAGE_WORDS) * 4;
    const int outg_smem  = (NSTAGE * A_STAGE_WORDS + NSTAGE * B1_STAGE_WORDS) * 4;
    const int flash_smem = (2 * KV_WORDS + 4 * P_WARP_WORDS) * 4;  // 73728 B

    cudaFuncSetAttribute(proj_gemm3_v2_kernel,
                         cudaFuncAttributeMaxDynamicSharedMemorySize, proj_smem);
    cudaFuncSetAttribute(gemm_v2_kernel<1>,
                         cudaFuncAttributeMaxDynamicSharedMemorySize, outg_smem);
    cudaFuncSetAttribute(flash_v5_kernel,
                         cudaFuncAttributeMaxDynamicSharedMemorySize, flash_smem);

    ProjArgs pa;
    pa.X[0] = Q;  pa.X[1] = K;  pa.X[2] = V;
    pa.W[0] = Wq; pa.W[1] = Wk; pa.W[2] = Wv;
    pa.bias[0] = bq; pa.bias[1] = bk; pa.bias[2] = bv;
    pa.out[0] = gq; pa.out[1] = gk; pa.out[2] = gv;

    dim3 pgrd(D_MODEL / 128, M_TOTAL / 128, 3);
    proj_gemm3_v2_kernel<<<pgrd, dim3(256), proj_smem>>>(pa);

    dim3 fgrd(SEQ / 128, BATCH * NUM_HEADS);
    flash_v5_kernel<<<fgrd, dim3(128), flash_smem>>>();

    dim3 ogrd(D_MODEL / 128, M_TOTAL / 128);
    gemm_v2_kernel<1><<<ogrd, dim3(256), outg_smem>>>(gcat, Wo, bo, out);
}

// round 7
// speedup vs baseline: 1.2500x; 1.2500x over previous
#include <cuda_runtime.h>
#include <math.h>
#include <stdint.h>

#define D_MODEL 1024
#define NUM_HEADS 16
#define DK 64
#define BATCH 2
#define SEQ 2048
#define M_TOTAL (BATCH * SEQ)  // 4096

// GEMM smem geometry (4-stage cp.async)
#define A_ROW_STRIDE 20
#define A_STAGE_WORDS (128 * A_ROW_STRIDE)
#define B0_STAGE_WORDS (16 * 136)
#define B1_STAGE_WORDS (128 * A_ROW_STRIDE)
#define NSTAGE 4

// flash smem strides (bank-tuned): K/P loads use gid*stride+tig -> stride%32==4;
// V loads use tig*stride+gid -> stride%32==8.
#define KRS 68
#define VRS 72
#define K_WORDS (64 * KRS)     // 4352
#define V_WORDS (64 * VRS)     // 4608
#define P_WORDS (128 * KRS)    // 8704

__device__ float g_q[BATCH * NUM_HEADS * SEQ * DK];
__device__ float g_k[BATCH * NUM_HEADS * SEQ * DK];
__device__ float g_v[BATCH * NUM_HEADS * SEQ * DK];
__device__ float g_cat[M_TOTAL * D_MODEL];

__device__ __forceinline__ uint32_t f2tf(float f) {
    uint32_t u;
    asm("cvt.rna.tf32.f32 %0, %1;" : "=r"(u) : "f"(f));
    return u;
}

__device__ __forceinline__ void mma_tf32(float* c, const uint32_t* a, const uint32_t* b) {
    asm volatile(
        "mma.sync.aligned.m16n8k8.row.col.f32.tf32.tf32.f32 "
        "{%0,%1,%2,%3}, {%4,%5,%6,%7}, {%8,%9}, {%0,%1,%2,%3};"
        : "+f"(c[0]), "+f"(c[1]), "+f"(c[2]), "+f"(c[3])
        : "r"(a[0]), "r"(a[1]), "r"(a[2]), "r"(a[3]), "r"(b[0]), "r"(b[1]));
}

__device__ __forceinline__ void cpa16(uint32_t* smem_dst, const float* gsrc) {
    uint32_t s = (uint32_t)__cvta_generic_to_shared(smem_dst);
    asm volatile("cp.async.cg.shared.global [%0], [%1], 16;" :: "r"(s), "l"(gsrc));
}
__device__ __forceinline__ void cpa_commit() {
    asm volatile("cp.async.commit_group;");
}
template <int N>
__device__ __forceinline__ void cpa_wait() {
    asm volatile("cp.async.wait_group %0;" :: "n"(N));
}

// =====================================================================
// TF32 GEMM: cp.async 4-stage pipeline, ONE sync per k-chunk.
// MODE 0 (proj): out[b,h,s,kd] = X @ W[h] + bias ; B smem xor-swizzled
// MODE 1 (out):  out[m,n] = X @ Wo[n,:]^T + bo  ; B smem row-major
// =====================================================================
template <int MODE>
__global__ __launch_bounds__(256, 2) void gemm_v3_kernel(
    const float* __restrict__ X, const float* __restrict__ W,
    const float* __restrict__ bias, float* __restrict__ out)
{
    extern __shared__ uint32_t sg[];
    uint32_t* smA = sg;
    uint32_t* smB = sg + NSTAGE * A_STAGE_WORDS;
    const int BSTW = (MODE == 0) ? B0_STAGE_WORDS : B1_STAGE_WORDS;

    const int t    = threadIdx.x;
    const int n0   = blockIdx.x * 128;
    const int m0   = blockIdx.y * 128;
    const int warp = t >> 5;
    const int lane = t & 31;
    const int gid  = lane >> 2;
    const int tig  = lane & 3;
    const int wm   = (warp & 1) * 64;
    const int wn   = (warp >> 1) * 32;

    const int am[2] = { (t + 0) >> 2, (t + 256) >> 2 };
    const int ak4   = (t & 3) << 2;

    float acc[4][4][4];
#pragma unroll
    for (int i = 0; i < 4; i++)
#pragma unroll
        for (int j = 0; j < 4; j++)
#pragma unroll
            for (int k = 0; k < 4; k++) acc[i][j][k] = 0.f;

    auto issue = [&](int stage, int kc) {
        uint32_t* As_ = smA + stage * A_STAGE_WORDS;
        uint32_t* Bs_ = smB + stage * BSTW;
#pragma unroll
        for (int rep = 0; rep < 2; rep++) {
            int m = am[rep];
            cpa16(As_ + m * A_ROW_STRIDE + ak4,
                  X + (size_t)(m0 + m) * D_MODEL + kc * 16 + ak4);
        }
#pragma unroll
        for (int rep = 0; rep < 2; rep++) {
            int f = t + rep * 256;
            if (MODE == 0) {
                int k = f >> 5, n4 = (f & 31) << 2;
                int bn = n0 + n4;
                int ck = ((k >> 2) & 3) << 2;
                cpa16(Bs_ + k * 136 + (n4 ^ ck),
                      W + (size_t)(bn >> 6) * (D_MODEL * DK)
                        + (size_t)(kc * 16 + k) * DK + (bn & 63));
            } else {
                int n = f >> 2, k4 = (f & 3) << 2;
                cpa16(Bs_ + n * A_ROW_STRIDE + k4,
                      W + (size_t)(n0 + n) * D_MODEL + kc * 16 + k4);
            }
        }
    };

    auto compute = [&](int stage) {
        uint32_t* As_ = smA + stage * A_STAGE_WORDS;
        uint32_t* Bs_ = smB + stage * BSTW;
#pragma unroll
        for (int ks = 0; ks < 2; ks++) {
            const int kb = ks * 8;
            uint32_t af[4][4];
#pragma unroll
            for (int mt = 0; mt < 4; mt++) {
                const int r = (wm + mt * 16 + gid) * A_ROW_STRIDE;
                af[mt][0] = As_[r + kb + tig];
                af[mt][1] = As_[r + 8 * A_ROW_STRIDE + kb + tig];
                af[mt][2] = As_[r + kb + tig + 4];
                af[mt][3] = As_[r + 8 * A_ROW_STRIDE + kb + tig + 4];
            }
            uint32_t bf[4][2];
#pragma unroll
            for (int nt = 0; nt < 4; nt++) {
                const int ncol = wn + nt * 8 + gid;
                if (MODE == 0) {
                    const int x0 = ks ? 8 : 0;
                    const int x1 = ks ? 12 : 4;
                    bf[nt][0] = Bs_[(kb + tig) * 136 + (ncol ^ x0)];
                    bf[nt][1] = Bs_[(kb + tig + 4) * 136 + (ncol ^ x1)];
                } else {
                    bf[nt][0] = Bs_[ncol * A_ROW_STRIDE + kb + tig];
                    bf[nt][1] = Bs_[ncol * A_ROW_STRIDE + kb + tig + 4];
                }
            }
#pragma unroll
            for (int mt = 0; mt < 4; mt++)
#pragma unroll
                for (int nt = 0; nt < 4; nt++) mma_tf32(acc[mt][nt], af[mt], bf[nt]);
        }
    };

    // 4-stage pipeline, one barrier per iteration
    issue(0, 0); cpa_commit();
    issue(1, 1); cpa_commit();
    issue(2, 2); cpa_commit();
    for (int kc = 0; kc < 64; kc++) {
        cpa_wait<2>();
        __syncthreads();
        compute(kc & 3);
        if (kc + 3 < 64) issue((kc + 3) & 3, kc + 3);
        cpa_commit();
    }

    // epilogue
#pragma unroll
    for (int mt = 0; mt < 4; mt++) {
#pragma unroll
        for (int nt = 0; nt < 4; nt++) {
            const int r0 = m0 + wm + mt * 16 + gid;
            const int r1 = r0 + 8;
            const int c  = n0 + wn + nt * 8 + tig * 2;
            const float bv0 = bias[c], bv1 = bias[c + 1];
            float2 v0 = make_float2(acc[mt][nt][0] + bv0, acc[mt][nt][1] + bv1);
            float2 v1 = make_float2(acc[mt][nt][2] + bv0, acc[mt][nt][3] + bv1);
            if (MODE == 0) {
                const int h = c >> 6, kd = c & 63;
                const int b0_ = r0 >> 11, s0 = r0 & 2047;
                const int b1_ = r1 >> 11, s1 = r1 & 2047;
                *(float2*)(out + (((size_t)b0_ * NUM_HEADS + h) * SEQ + s0) * DK + kd) = v0;
                *(float2*)(out + (((size_t)b1_ * NUM_HEADS + h) * SEQ + s1) * DK + kd) = v1;
            } else {
                *(float2*)(out + (size_t)r0 * D_MODEL + c) = v0;
                *(float2*)(out + (size_t)r1 * D_MODEL + c) = v1;
            }
        }
    }
}

// proj wrapper: grid.z selects Q/K/V
struct ProjArgs {
    const float* X[3];
    const float* W[3];
    const float* bias[3];
    float* out[3];
};

__global__ __launch_bounds__(256, 2) void proj_gemm3_v3_kernel(ProjArgs args)
{
    extern __shared__ uint32_t sg[];
    const int z = blockIdx.z;
    const float* X    = args.X[z];
    const float* W    = args.W[z];
    const float* bias = args.bias[z];
    float* out        = args.out[z];

    uint32_t* smA = sg;
    uint32_t* smB = sg + NSTAGE * A_STAGE_WORDS;

    const int t    = threadIdx.x;
    const int n0   = blockIdx.x * 128;
    const int m0   = blockIdx.y * 128;
    const int warp = t >> 5;
    const int lane = t & 31;
    const int gid  = lane >> 2;
    const int tig  = lane & 3;
    const int wm   = (warp & 1) * 64;
    const int wn   = (warp >> 1) * 32;

    const int am[2] = { (t + 0) >> 2, (t + 256) >> 2 };
    const int ak4   = (t & 3) << 2;

    float acc[4][4][4];
#pragma unroll
    for (int i = 0; i < 4; i++)
#pragma unroll
        for (int j = 0; j < 4; j++)
#pragma unroll
            for (int k = 0; k < 4; k++) acc[i][j][k] = 0.f;

    auto issue = [&](int stage, int kc) {
        uint32_t* As_ = smA + stage * A_STAGE_WORDS;
        uint32_t* Bs_ = smB + stage * B0_STAGE_WORDS;
#pragma unroll
        for (int rep = 0; rep < 2; rep++) {
            int m = am[rep];
            cpa16(As_ + m * A_ROW_STRIDE + ak4,
                  X + (size_t)(m0 + m) * D_MODEL + kc * 16 + ak4);
        }
#pragma unroll
        for (int rep = 0; rep < 2; rep++) {
            int f = t + rep * 256;
            int k = f >> 5, n4 = (f & 31) << 2;
            int bn = n0 + n4;
            int ck = ((k >> 2) & 3) << 2;
            cpa16(Bs_ + k * 136 + (n4 ^ ck),
                  W + (size_t)(bn >> 6) * (D_MODEL * DK)
                    + (size_t)(kc * 16 + k) * DK + (bn & 63));
        }
    };

    auto compute = [&](int stage) {
        uint32_t* As_ = smA + stage * A_STAGE_WORDS;
        uint32_t* Bs_ = smB + stage * B0_STAGE_WORDS;
#pragma unroll
        for (int ks = 0; ks < 2; ks++) {
            const int kb = ks * 8;
            const int x0 = ks ? 8 : 0;
            const int x1 = ks ? 12 : 4;
            uint32_t af[4][4];
#pragma unroll
            for (int mt = 0; mt < 4; mt++) {
                const int r = (wm + mt * 16 + gid) * A_ROW_STRIDE;
                af[mt][0] = As_[r + kb + tig];
                af[mt][1] = As_[r + 8 * A_ROW_STRIDE + kb + tig];
                af[mt][2] = As_[r + kb + tig + 4];
                af[mt][3] = As_[r + 8 * A_ROW_STRIDE + kb + tig + 4];
            }
            uint32_t bf[4][2];
#pragma unroll
            for (int nt = 0; nt < 4; nt++) {
                const int ncol = wn + nt * 8 + gid;
                bf[nt][0] = Bs_[(kb + tig) * 136 + (ncol ^ x0)];
                bf[nt][1] = Bs_[(kb + tig + 4) * 136 + (ncol ^ x1)];
            }
#pragma unroll
            for (int mt = 0; mt < 4; mt++)
#pragma unroll
                for (int nt = 0; nt < 4; nt++) mma_tf32(acc[mt][nt], af[mt], bf[nt]);
        }
    };

    issue(0, 0); cpa_commit();
    issue(1, 1); cpa_commit();
    issue(2, 2); cpa_commit();
    for (int kc = 0; kc < 64; kc++) {
        cpa_wait<2>();
        __syncthreads();
        compute(kc & 3);
        if (kc + 3 < 64) issue((kc + 3) & 3, kc + 3);
        cpa_commit();
    }

#pragma unroll
    for (int mt = 0; mt < 4; mt++) {
#pragma unroll
        for (int nt = 0; nt < 4; nt++) {
            const int r0 = m0 + wm + mt * 16 + gid;
            const int r1 = r0 + 8;
            const int c  = n0 + wn + nt * 8 + tig * 2;
            const float bv0 = bias[c], bv1 = bias[c + 1];
            float2 v0 = make_float2(acc[mt][nt][0] + bv0, acc[mt][nt][1] + bv1);
            float2 v1 = make_float2(acc[mt][nt][2] + bv0, acc[mt][nt][3] + bv1);
            const int h = c >> 6, kd = c & 63;
            const int b0_ = r0 >> 11, s0 = r0 & 2047;
            const int b1_ = r1 >> 11, s1 = r1 & 2047;
            *(float2*)(out + (((size_t)b0_ * NUM_HEADS + h) * SEQ + s0) * DK + kd) = v0;
            *(float2*)(out + (((size_t)b1_ * NUM_HEADS + h) * SEQ + s1) * DK + kd) = v1;
        }
    }
}

// =====================================================================
// Flash attention (R3 skeleton, bank-tuned strides: Ks/P 68, Vs 72).
// 256 threads / 8 warps, Bq=128, Bkv=64.
// =====================================================================
__global__ __launch_bounds__(256) void flash_mma_kernel()
{
    extern __shared__ uint32_t smu[];
    uint32_t* Ks = smu;                       // [64][KRS]
    uint32_t* Vs = smu + K_WORDS;             // [64][VRS]
    uint32_t* Ss = smu + K_WORDS + V_WORDS;   // [128][KRS]

    const int t    = threadIdx.x;
    const int warp = t >> 5;
    const int lane = t & 31;
    const int gid  = lane >> 2;
    const int tig  = lane & 3;
    const int q0   = blockIdx.x * 128;
    const int bh   = blockIdx.y;

    const float* qb = g_q + (size_t)bh * SEQ * DK;
    const float* kb = g_k + (size_t)bh * SEQ * DK;
    const float* vb = g_v + (size_t)bh * SEQ * DK;

    const int r0 = q0 + warp * 16 + gid;
    const int r1 = r0 + 8;
    uint32_t qf[8][4];
#pragma unroll
    for (int kk = 0; kk < 8; kk++) {
        qf[kk][0] = f2tf(qb[(size_t)r0 * DK + kk * 8 + tig]     * 0.125f);
        qf[kk][1] = f2tf(qb[(size_t)r1 * DK + kk * 8 + tig]     * 0.125f);
        qf[kk][2] = f2tf(qb[(size_t)r0 * DK + kk * 8 + tig + 4] * 0.125f);
        qf[kk][3] = f2tf(qb[(size_t)r1 * DK + kk * 8 + tig + 4] * 0.125f);
    }

    uint32_t* Sw = Ss + warp * 16 * KRS;

    float m0 = -INFINITY, m1 = -INFINITY, l0 = 0.f, l1 = 0.f;
    float o[8][4];
#pragma unroll
    for (int j = 0; j < 8; j++)
#pragma unroll
        for (int k = 0; k < 4; k++) o[j][k] = 0.f;

    for (int s0 = 0; s0 < SEQ; s0 += 64) {
        __syncthreads();
#pragma unroll
        for (int rep = 0; rep < 4; rep++) {
            int f = t + rep * 256;
            int row = f >> 4, c4 = (f & 15) << 2;
            float4 kv = *(const float4*)&kb[(size_t)(s0 + row) * DK + c4];
            float4 vv = *(const float4*)&vb[(size_t)(s0 + row) * DK + c4];
            uint4 kt = make_uint4(f2tf(kv.x), f2tf(kv.y), f2tf(kv.z), f2tf(kv.w));
            uint4 vt = make_uint4(f2tf(vv.x), f2tf(vv.y), f2tf(vv.z), f2tf(vv.w));
            *(uint4*)&Ks[row * KRS + c4] = kt;
            *(uint4*)&Vs[row * VRS + c4] = vt;
        }
        __syncthreads();

        float sacc[8][4];
#pragma unroll
        for (int j = 0; j < 8; j++)
#pragma unroll
            for (int k = 0; k < 4; k++) sacc[j][k] = 0.f;
#pragma unroll
        for (int kk = 0; kk < 8; kk++) {
            uint32_t bf[8][2];
#pragma unroll
            for (int j = 0; j < 8; j++) {
                bf[j][0] = Ks[(j * 8 + gid) * KRS + kk * 8 + tig];
                bf[j][1] = Ks[(j * 8 + gid) * KRS + kk * 8 + tig + 4];
            }
#pragma unroll
            for (int j = 0; j < 8; j++) mma_tf32(sacc[j], qf[kk], bf[j]);
        }

        float t0 = -INFINITY, t1 = -INFINITY;
#pragma unroll
        for (int j = 0; j < 8; j++) {
            t0 = fmaxf(t0, fmaxf(sacc[j][0], sacc[j][1]));
            t1 = fmaxf(t1, fmaxf(sacc[j][2], sacc[j][3]));
        }
        t0 = fmaxf(t0, __shfl_xor_sync(0xffffffffu, t0, 1));
        t0 = fmaxf(t0, __shfl_xor_sync(0xffffffffu, t0, 2));
        t1 = fmaxf(t1, __shfl_xor_sync(0xffffffffu, t1, 1));
        t1 = fmaxf(t1, __shfl_xor_sync(0xffffffffu, t1, 2));

        float nm0 = fmaxf(m0, t0), nm1 = fmaxf(m1, t1);
        float a0 = __expf(m0 - nm0), a1 = __expf(m1 - nm1);
        m0 = nm0; m1 = nm1;

        float p0 = 0.f, p1 = 0.f;
#pragma unroll
        for (int j = 0; j < 8; j++) {
            float e0 = __expf(sacc[j][0] - nm0);
            float e1 = __expf(sacc[j][1] - nm0);
            float e2 = __expf(sacc[j][2] - nm1);
            float e3 = __expf(sacc[j][3] - nm1);
            p0 += e0 + e1;
            p1 += e2 + e3;
            uint2 w0 = make_uint2(f2tf(e0), f2tf(e1));
            uint2 w1 = make_uint2(f2tf(e2), f2tf(e3));
            *(uint2*)&Sw[gid * KRS + j * 8 + tig * 2]       = w0;
            *(uint2*)&Sw[(gid + 8) * KRS + j * 8 + tig * 2] = w1;
        }
        p0 += __shfl_xor_sync(0xffffffffu, p0, 1);
        p0 += __shfl_xor_sync(0xffffffffu, p0, 2);
        p1 += __shfl_xor_sync(0xffffffffu, p1, 1);
        p1 += __shfl_xor_sync(0xffffffffu, p1, 2);
        l0 = l0 * a0 + p0;
        l1 = l1 * a1 + p1;

#pragma unroll
        for (int j = 0; j < 8; j++) {
            o[j][0] *= a0; o[j][1] *= a0;
            o[j][2] *= a1; o[j][3] *= a1;
        }
        __syncwarp();

#pragma unroll
        for (int kk = 0; kk < 8; kk++) {
            uint32_t af[4];
            af[0] = Sw[gid * KRS + kk * 8 + tig];
            af[1] = Sw[(gid + 8) * KRS + kk * 8 + tig];
            af[2] = Sw[gid * KRS + kk * 8 + tig + 4];
            af[3] = Sw[(gid + 8) * KRS + kk * 8 + tig + 4];
#pragma unroll
            for (int j = 0; j < 8; j++) {
                uint32_t bf[2];
                bf[0] = Vs[(kk * 8 + tig) * VRS + j * 8 + gid];
                bf[1] = Vs[(kk * 8 + tig + 4) * VRS + j * 8 + gid];
                mma_tf32(o[j], af, bf);
            }
        }
        __syncwarp();
    }

    const float i0 = 1.f / l0, i1 = 1.f / l1;
    const int b_ = bh >> 4, h = bh & 15;
    float* row0 = g_cat + (size_t)(b_ * SEQ + r0) * D_MODEL + h * DK;
    float* row1 = g_cat + (size_t)(b_ * SEQ + r1) * D_MODEL + h * DK;
#pragma unroll
    for (int j = 0; j < 8; j++) {
        *(float2*)(row0 + j * 8 + tig * 2) = make_float2(o[j][0] * i0, o[j][1] * i0);
        *(float2*)(row1 + j * 8 + tig * 2) = make_float2(o[j][2] * i1, o[j][3] * i1);
    }
}

extern "C" void kernel_launch(void* const* d_in, const int* in_sizes, int n_in,
                              void* d_out, int out_size)
{
    const float* Q  = (const float*)d_in[0];
    const float* K  = (const float*)d_in[1];
    const float* V  = (const float*)d_in[2];
    const float* Wq = (const float*)d_in[3];
    const float* bq = (const float*)d_in[4];
    const float* Wk = (const float*)d_in[5];
    const float* bk = (const float*)d_in[6];
    const float* Wv = (const float*)d_in[7];
    const float* bv = (const float*)d_in[8];
    const float* Wo = (const float*)d_in[9];
    const float* bo = (const float*)d_in[10];
    float* out = (float*)d_out;

    float *gq, *gk, *gv, *gcat;
    cudaGetSymbolAddress((void**)&gq, g_q);
    cudaGetSymbolAddress((void**)&gk, g_k);
    cudaGetSymbolAddress((void**)&gv, g_v);
    cudaGetSymbolAddress((void**)&gcat, g_cat);

    const int proj_smem  = (NSTAGE * A_STAGE_WORDS + NSTAGE * B0_STAGE_WORDS) * 4; // 75776
    const int outg_smem  = (NSTAGE * A_STAGE_WORDS + NSTAGE * B1_STAGE_WORDS) * 4; // 81920
    const int flash_smem = (K_WORDS + V_WORDS + P_WORDS) * 4;                      // 70656

    cudaFuncSetAttribute(proj_gemm3_v3_kernel,
                         cudaFuncAttributeMaxDynamicSharedMemorySize, proj_smem);
    cudaFuncSetAttribute(gemm_v3_kernel<1>,
                         cudaFuncAttributeMaxDynamicSharedMemorySize, outg_smem);
    cudaFuncSetAttribute(flash_mma_kernel,
                         cudaFuncAttributeMaxDynamicSharedMemorySize, flash_smem);

    ProjArgs pa;
    pa.X[0] = Q;  pa.X[1] = K;  pa.X[2] = V;
    pa.W[0] = Wq; pa.W[1] = Wk; pa.W[2] = Wv;
    pa.bias[0] = bq; pa.bias[1] = bk; pa.bias[2] = bv;
    pa.out[0] = gq; pa.out[1] = gk; pa.out[2] = gv;

    dim3 pgrd(D_MODEL / 128, M_TOTAL / 128, 3);
    proj_gemm3_v3_kernel<<<pgrd, dim3(256), proj_smem>>>(pa);

    dim3 fgrd(SEQ / 128, BATCH * NUM_HEADS);
    flash_mma_kernel<<<fgrd, dim3(256), flash_smem>>>();

    dim3 ogrd(D_MODEL / 128, M_TOTAL / 128);
    gemm_v3_kernel<1><<<ogrd, dim3(256), outg_smem>>>(gcat, Wo, bo, out);
}

// round 8
// speedup vs baseline: 1.2999x; 1.0398x over previous
#include <cuda_runtime.h>
#include <math.h>
#include <stdint.h>

#define D_MODEL 1024
#define NUM_HEADS 16
#define DK 64
#define BATCH 2
#define SEQ 2048
#define M_TOTAL (BATCH * SEQ)  // 4096

// GEMM smem geometry (4-stage cp.async)
#define A_ROW_STRIDE 20
#define A_STAGE_WORDS (128 * A_ROW_STRIDE)
#define B0_STAGE_WORDS (16 * 136)
#define B1_STAGE_WORDS (128 * A_ROW_STRIDE)
#define NSTAGE 4

// flash smem strides (bank-tuned): K/P loads use gid*stride+tig -> stride%32==4;
// V loads use tig*stride+gid -> stride%32==8. K/V double-buffered (cp.async).
#define KRS 68
#define VRS 72
#define KB_WORDS (64 * KRS)     // 4352 per buffer
#define VB_WORDS (64 * VRS)     // 4608 per buffer
#define P_WORDS (128 * KRS)     // 8704

__device__ float g_q[BATCH * NUM_HEADS * SEQ * DK];
__device__ float g_k[BATCH * NUM_HEADS * SEQ * DK];
__device__ float g_v[BATCH * NUM_HEADS * SEQ * DK];
__device__ float g_cat[M_TOTAL * D_MODEL];

__device__ __forceinline__ uint32_t f2tf(float f) {
    uint32_t u;
    asm("cvt.rna.tf32.f32 %0, %1;" : "=r"(u) : "f"(f));
    return u;
}

__device__ __forceinline__ void mma_tf32(float* c, const uint32_t* a, const uint32_t* b) {
    asm volatile(
        "mma.sync.aligned.m16n8k8.row.col.f32.tf32.tf32.f32 "
        "{%0,%1,%2,%3}, {%4,%5,%6,%7}, {%8,%9}, {%0,%1,%2,%3};"
        : "+f"(c[0]), "+f"(c[1]), "+f"(c[2]), "+f"(c[3])
        : "r"(a[0]), "r"(a[1]), "r"(a[2]), "r"(a[3]), "r"(b[0]), "r"(b[1]));
}

__device__ __forceinline__ void cpa16(uint32_t* smem_dst, const float* gsrc) {
    uint32_t s = (uint32_t)__cvta_generic_to_shared(smem_dst);
    asm volatile("cp.async.cg.shared.global [%0], [%1], 16;" :: "r"(s), "l"(gsrc));
}
__device__ __forceinline__ void cpa_commit() {
    asm volatile("cp.async.commit_group;");
}
template <int N>
__device__ __forceinline__ void cpa_wait() {
    asm volatile("cp.async.wait_group %0;" :: "n"(N));
}

// =====================================================================
// TF32 GEMM (R7, known-good): cp.async 4-stage, ONE sync per k-chunk.
// =====================================================================
template <int MODE>
__global__ __launch_bounds__(256, 2) void gemm_v3_kernel(
    const float* __restrict__ X, const float* __restrict__ W,
    const float* __restrict__ bias, float* __restrict__ out)
{
    extern __shared__ uint32_t sg[];
    uint32_t* smA = sg;
    uint32_t* smB = sg + NSTAGE * A_STAGE_WORDS;
    const int BSTW = (MODE == 0) ? B0_STAGE_WORDS : B1_STAGE_WORDS;

    const int t    = threadIdx.x;
    const int n0   = blockIdx.x * 128;
    const int m0   = blockIdx.y * 128;
    const int warp = t >> 5;
    const int lane = t & 31;
    const int gid  = lane >> 2;
    const int tig  = lane & 3;
    const int wm   = (warp & 1) * 64;
    const int wn   = (warp >> 1) * 32;

    const int am[2] = { (t + 0) >> 2, (t + 256) >> 2 };
    const int ak4   = (t & 3) << 2;

    float acc[4][4][4];
#pragma unroll
    for (int i = 0; i < 4; i++)
#pragma unroll
        for (int j = 0; j < 4; j++)
#pragma unroll
            for (int k = 0; k < 4; k++) acc[i][j][k] = 0.f;

    auto issue = [&](int stage, int kc) {
        uint32_t* As_ = smA + stage * A_STAGE_WORDS;
        uint32_t* Bs_ = smB + stage * BSTW;
#pragma unroll
        for (int rep = 0; rep < 2; rep++) {
            int m = am[rep];
            cpa16(As_ + m * A_ROW_STRIDE + ak4,
                  X + (size_t)(m0 + m) * D_MODEL + kc * 16 + ak4);
        }
#pragma unroll
        for (int rep = 0; rep < 2; rep++) {
            int f = t + rep * 256;
            if (MODE == 0) {
                int k = f >> 5, n4 = (f & 31) << 2;
                int bn = n0 + n4;
                int ck = ((k >> 2) & 3) << 2;
                cpa16(Bs_ + k * 136 + (n4 ^ ck),
                      W + (size_t)(bn >> 6) * (D_MODEL * DK)
                        + (size_t)(kc * 16 + k) * DK + (bn & 63));
            } else {
                int n = f >> 2, k4 = (f & 3) << 2;
                cpa16(Bs_ + n * A_ROW_STRIDE + k4,
                      W + (size_t)(n0 + n) * D_MODEL + kc * 16 + k4);
            }
        }
    };

    auto compute = [&](int stage) {
        uint32_t* As_ = smA + stage * A_STAGE_WORDS;
        uint32_t* Bs_ = smB + stage * BSTW;
#pragma unroll
        for (int ks = 0; ks < 2; ks++) {
            const int kb = ks * 8;
            uint32_t af[4][4];
#pragma unroll
            for (int mt = 0; mt < 4; mt++) {
                const int r = (wm + mt * 16 + gid) * A_ROW_STRIDE;
                af[mt][0] = As_[r + kb + tig];
                af[mt][1] = As_[r + 8 * A_ROW_STRIDE + kb + tig];
                af[mt][2] = As_[r + kb + tig + 4];
                af[mt][3] = As_[r + 8 * A_ROW_STRIDE + kb + tig + 4];
            }
            uint32_t bf[4][2];
#pragma unroll
            for (int nt = 0; nt < 4; nt++) {
                const int ncol = wn + nt * 8 + gid;
                if (MODE == 0) {
                    const int x0 = ks ? 8 : 0;
                    const int x1 = ks ? 12 : 4;
                    bf[nt][0] = Bs_[(kb + tig) * 136 + (ncol ^ x0)];
                    bf[nt][1] = Bs_[(kb + tig + 4) * 136 + (ncol ^ x1)];
                } else {
                    bf[nt][0] = Bs_[ncol * A_ROW_STRIDE + kb + tig];
                    bf[nt][1] = Bs_[ncol * A_ROW_STRIDE + kb + tig + 4];
                }
            }
#pragma unroll
            for (int mt = 0; mt < 4; mt++)
#pragma unroll
                for (int nt = 0; nt < 4; nt++) mma_tf32(acc[mt][nt], af[mt], bf[nt]);
        }
    };

    issue(0, 0); cpa_commit();
    issue(1, 1); cpa_commit();
    issue(2, 2); cpa_commit();
    for (int kc = 0; kc < 64; kc++) {
        cpa_wait<2>();
        __syncthreads();
        compute(kc & 3);
        if (kc + 3 < 64) issue((kc + 3) & 3, kc + 3);
        cpa_commit();
    }

#pragma unroll
    for (int mt = 0; mt < 4; mt++) {
#pragma unroll
        for (int nt = 0; nt < 4; nt++) {
            const int r0 = m0 + wm + mt * 16 + gid;
            const int r1 = r0 + 8;
            const int c  = n0 + wn + nt * 8 + tig * 2;
            const float bv0 = bias[c], bv1 = bias[c + 1];
            float2 v0 = make_float2(acc[mt][nt][0] + bv0, acc[mt][nt][1] + bv1);
            float2 v1 = make_float2(acc[mt][nt][2] + bv0, acc[mt][nt][3] + bv1);
            if (MODE == 0) {
                const int h = c >> 6, kd = c & 63;
                const int b0_ = r0 >> 11, s0 = r0 & 2047;
                const int b1_ = r1 >> 11, s1 = r1 & 2047;
                *(float2*)(out + (((size_t)b0_ * NUM_HEADS + h) * SEQ + s0) * DK + kd) = v0;
                *(float2*)(out + (((size_t)b1_ * NUM_HEADS + h) * SEQ + s1) * DK + kd) = v1;
            } else {
                *(float2*)(out + (size_t)r0 * D_MODEL + c) = v0;
                *(float2*)(out + (size_t)r1 * D_MODEL + c) = v1;
            }
        }
    }
}

// proj wrapper (R7, known-good): grid.z selects Q/K/V
struct ProjArgs {
    const float* X[3];
    const float* W[3];
    const float* bias[3];
    float* out[3];
};

__global__ __launch_bounds__(256, 2) void proj_gemm3_v3_kernel(ProjArgs args)
{
    extern __shared__ uint32_t sg[];
    const int z = blockIdx.z;
    const float* X    = args.X[z];
    const float* W    = args.W[z];
    const float* bias = args.bias[z];
    float* out        = args.out[z];

    uint32_t* smA = sg;
    uint32_t* smB = sg + NSTAGE * A_STAGE_WORDS;

    const int t    = threadIdx.x;
    const int n0   = blockIdx.x * 128;
    const int m0   = blockIdx.y * 128;
    const int warp = t >> 5;
    const int lane = t & 31;
    const int gid  = lane >> 2;
    const int tig  = lane & 3;
    const int wm   = (warp & 1) * 64;
    const int wn   = (warp >> 1) * 32;

    const int am[2] = { (t + 0) >> 2, (t + 256) >> 2 };
    const int ak4   = (t & 3) << 2;

    float acc[4][4][4];
#pragma unroll
    for (int i = 0; i < 4; i++)
#pragma unroll
        for (int j = 0; j < 4; j++)
#pragma unroll
            for (int k = 0; k < 4; k++) acc[i][j][k] = 0.f;

    auto issue = [&](int stage, int kc) {
        uint32_t* As_ = smA + stage * A_STAGE_WORDS;
        uint32_t* Bs_ = smB + stage * B0_STAGE_WORDS;
#pragma unroll
        for (int rep = 0; rep < 2; rep++) {
            int m = am[rep];
            cpa16(As_ + m * A_ROW_STRIDE + ak4,
                  X + (size_t)(m0 + m) * D_MODEL + kc * 16 + ak4);
        }
#pragma unroll
        for (int rep = 0; rep < 2; rep++) {
            int f = t + rep * 256;
            int k = f >> 5, n4 = (f & 31) << 2;
            int bn = n0 + n4;
            int ck = ((k >> 2) & 3) << 2;
            cpa16(Bs_ + k * 136 + (n4 ^ ck),
                  W + (size_t)(bn >> 6) * (D_MODEL * DK)
                    + (size_t)(kc * 16 + k) * DK + (bn & 63));
        }
    };

    auto compute = [&](int stage) {
        uint32_t* As_ = smA + stage * A_STAGE_WORDS;
        uint32_t* Bs_ = smB + stage * B0_STAGE_WORDS;
#pragma unroll
        for (int ks = 0; ks < 2; ks++) {
            const int kb = ks * 8;
            const int x0 = ks ? 8 : 0;
            const int x1 = ks ? 12 : 4;
            uint32_t af[4][4];
#pragma unroll
            for (int mt = 0; mt < 4; mt++) {
                const int r = (wm + mt * 16 + gid) * A_ROW_STRIDE;
                af[mt][0] = As_[r + kb + tig];
                af[mt][1] = As_[r + 8 * A_ROW_STRIDE + kb + tig];
                af[mt][2] = As_[r + kb + tig + 4];
                af[mt][3] = As_[r + 8 * A_ROW_STRIDE + kb + tig + 4];
            }
            uint32_t bf[4][2];
#pragma unroll
            for (int nt = 0; nt < 4; nt++) {
                const int ncol = wn + nt * 8 + gid;
                bf[nt][0] = Bs_[(kb + tig) * 136 + (ncol ^ x0)];
                bf[nt][1] = Bs_[(kb + tig + 4) * 136 + (ncol ^ x1)];
            }
#pragma unroll
            for (int mt = 0; mt < 4; mt++)
#pragma unroll
                for (int nt = 0; nt < 4; nt++) mma_tf32(acc[mt][nt], af[mt], bf[nt]);
        }
    };

    issue(0, 0); cpa_commit();
    issue(1, 1); cpa_commit();
    issue(2, 2); cpa_commit();
    for (int kc = 0; kc < 64; kc++) {
        cpa_wait<2>();
        __syncthreads();
        compute(kc & 3);
        if (kc + 3 < 64) issue((kc + 3) & 3, kc + 3);
        cpa_commit();
    }

#pragma unroll
    for (int mt = 0; mt < 4; mt++) {
#pragma unroll
        for (int nt = 0; nt < 4; nt++) {
            const int r0 = m0 + wm + mt * 16 + gid;
            const int r1 = r0 + 8;
            const int c  = n0 + wn + nt * 8 + tig * 2;
            const float bv0 = bias[c], bv1 = bias[c + 1];
            float2 v0 = make_float2(acc[mt][nt][0] + bv0, acc[mt][nt][1] + bv1);
            float2 v1 = make_float2(acc[mt][nt][2] + bv0, acc[mt][nt][3] + bv1);
            const int h = c >> 6, kd = c & 63;
            const int b0_ = r0 >> 11, s0 = r0 & 2047;
            const int b1_ = r1 >> 11, s1 = r1 & 2047;
            *(float2*)(out + (((size_t)b0_ * NUM_HEADS + h) * SEQ + s0) * DK + kd) = v0;
            *(float2*)(out + (((size_t)b1_ * NUM_HEADS + h) * SEQ + s1) * DK + kd) = v1;
        }
    }
}

// =====================================================================
// Flash attention v6: R7 skeleton + cp.async double-buffered K/V
// (raw fp32 in smem, HW tf32 truncation in mma). One wait+sync per tile;
// next tile's copy overlaps current compute.
// =====================================================================
__global__ __launch_bounds__(256) void flash_mma_kernel()
{
    extern __shared__ uint32_t smu[];
    uint32_t* KsB = smu;                             // 2 x [64][KRS]
    uint32_t* VsB = smu + 2 * KB_WORDS;              // 2 x [64][VRS]
    uint32_t* Ss  = smu + 2 * KB_WORDS + 2 * VB_WORDS; // [128][KRS]

    const int t    = threadIdx.x;
    const int warp = t >> 5;
    const int lane = t & 31;
    const int gid  = lane >> 2;
    const int tig  = lane & 3;
    const int q0   = blockIdx.x * 128;
    const int bh   = blockIdx.y;

    const float* qb = g_q + (size_t)bh * SEQ * DK;
    const float* kb = g_k + (size_t)bh * SEQ * DK;
    const float* vb = g_v + (size_t)bh * SEQ * DK;

    const int r0 = q0 + warp * 16 + gid;
    const int r1 = r0 + 8;
    uint32_t qf[8][4];
#pragma unroll
    for (int kk = 0; kk < 8; kk++) {
        qf[kk][0] = f2tf(qb[(size_t)r0 * DK + kk * 8 + tig]     * 0.125f);
        qf[kk][1] = f2tf(qb[(size_t)r1 * DK + kk * 8 + tig]     * 0.125f);
        qf[kk][2] = f2tf(qb[(size_t)r0 * DK + kk * 8 + tig + 4] * 0.125f);
        qf[kk][3] = f2tf(qb[(size_t)r1 * DK + kk * 8 + tig + 4] * 0.125f);
    }

    uint32_t* Sw = Ss + warp * 16 * KRS;

    float m0 = -INFINITY, m1 = -INFINITY, l0 = 0.f, l1 = 0.f;
    float o[8][4];
#pragma unroll
    for (int j = 0; j < 8; j++)
#pragma unroll
        for (int k = 0; k < 4; k++) o[j][k] = 0.f;

    // per-thread copy coords: 4 chunks of 16B per matrix per tile
    const int crow[4] = { (t + 0) >> 4, (t + 256) >> 4, (t + 512) >> 4, (t + 768) >> 4 };
    const int cc4     = (t & 15) << 2;

    auto issue_kv = [&](int buf, int s0) {
        uint32_t* Ks_ = KsB + buf * KB_WORDS;
        uint32_t* Vs_ = VsB + buf * VB_WORDS;
#pragma unroll
        for (int rep = 0; rep < 4; rep++) {
            int row = crow[rep];
            cpa16(Ks_ + row * KRS + cc4, kb + (size_t)(s0 + row) * DK + cc4);
            cpa16(Vs_ + row * VRS + cc4, vb + (size_t)(s0 + row) * DK + cc4);
        }
        cpa_commit();
    };

    issue_kv(0, 0);

    for (int tile = 0; tile < SEQ / 64; tile++) {
        const int buf = tile & 1;
        uint32_t* Ks = KsB + buf * KB_WORDS;
        uint32_t* Vs = VsB + buf * VB_WORDS;

        cpa_wait<0>();
        __syncthreads();
        if (tile + 1 < SEQ / 64) issue_kv(buf ^ 1, (tile + 1) * 64);

        // ---- S = Q K^T ----
        float sacc[8][4];
#pragma unroll
        for (int j = 0; j < 8; j++)
#pragma unroll
            for (int k = 0; k < 4; k++) sacc[j][k] = 0.f;
#pragma unroll
        for (int kk = 0; kk < 8; kk++) {
            uint32_t bf[8][2];
#pragma unroll
            for (int j = 0; j < 8; j++) {
                bf[j][0] = Ks[(j * 8 + gid) * KRS + kk * 8 + tig];
                bf[j][1] = Ks[(j * 8 + gid) * KRS + kk * 8 + tig + 4];
            }
#pragma unroll
            for (int j = 0; j < 8; j++) mma_tf32(sacc[j], qf[kk], bf[j]);
        }

        // ---- fragment-resident online softmax ----
        float t0 = -INFINITY, t1 = -INFINITY;
#pragma unroll
        for (int j = 0; j < 8; j++) {
            t0 = fmaxf(t0, fmaxf(sacc[j][0], sacc[j][1]));
            t1 = fmaxf(t1, fmaxf(sacc[j][2], sacc[j][3]));
        }
        t0 = fmaxf(t0, __shfl_xor_sync(0xffffffffu, t0, 1));
        t0 = fmaxf(t0, __shfl_xor_sync(0xffffffffu, t0, 2));
        t1 = fmaxf(t1, __shfl_xor_sync(0xffffffffu, t1, 1));
        t1 = fmaxf(t1, __shfl_xor_sync(0xffffffffu, t1, 2));

        float nm0 = fmaxf(m0, t0), nm1 = fmaxf(m1, t1);
        float a0 = __expf(m0 - nm0), a1 = __expf(m1 - nm1);
        m0 = nm0; m1 = nm1;

        float p0 = 0.f, p1 = 0.f;
#pragma unroll
        for (int j = 0; j < 8; j++) {
            float e0 = __expf(sacc[j][0] - nm0);
            float e1 = __expf(sacc[j][1] - nm0);
            float e2 = __expf(sacc[j][2] - nm1);
            float e3 = __expf(sacc[j][3] - nm1);
            p0 += e0 + e1;
            p1 += e2 + e3;
            uint2 w0 = make_uint2(f2tf(e0), f2tf(e1));
            uint2 w1 = make_uint2(f2tf(e2), f2tf(e3));
            *(uint2*)&Sw[gid * KRS + j * 8 + tig * 2]       = w0;
            *(uint2*)&Sw[(gid + 8) * KRS + j * 8 + tig * 2] = w1;
        }
        p0 += __shfl_xor_sync(0xffffffffu, p0, 1);
        p0 += __shfl_xor_sync(0xffffffffu, p0, 2);
        p1 += __shfl_xor_sync(0xffffffffu, p1, 1);
        p1 += __shfl_xor_sync(0xffffffffu, p1, 2);
        l0 = l0 * a0 + p0;
        l1 = l1 * a1 + p1;

#pragma unroll
        for (int j = 0; j < 8; j++) {
            o[j][0] *= a0; o[j][1] *= a0;
            o[j][2] *= a1; o[j][3] *= a1;
        }
        __syncwarp();

        // ---- O += P V ----
#pragma unroll
        for (int kk = 0; kk < 8; kk++) {
            uint32_t af[4];
            af[0] = Sw[gid * KRS + kk * 8 + tig];
            af[1] = Sw[(gid + 8) * KRS + kk * 8 + tig];
            af[2] = Sw[gid * KRS + kk * 8 + tig + 4];
            af[3] = Sw[(gid + 8) * KRS + kk * 8 + tig + 4];
#pragma unroll
            for (int j = 0; j < 8; j++) {
                uint32_t bf[2];
                bf[0] = Vs[(kk * 8 + tig) * VRS + j * 8 + gid];
                bf[1] = Vs[(kk * 8 + tig + 4) * VRS + j * 8 + gid];
                mma_tf32(o[j], af, bf);
            }
        }
        __syncwarp();
    }

    const float i0 = 1.f / l0, i1 = 1.f / l1;
    const int b_ = bh >> 4, h = bh & 15;
    float* row0 = g_cat + (size_t)(b_ * SEQ + r0) * D_MODEL + h * DK;
    float* row1 = g_cat + (size_t)(b_ * SEQ + r1) * D_MODEL + h * DK;
#pragma unroll
    for (int j = 0; j < 8; j++) {
        *(float2*)(row0 + j * 8 + tig * 2) = make_float2(o[j][0] * i0, o[j][1] * i0);
        *(float2*)(row1 + j * 8 + tig * 2) = make_float2(o[j][2] * i1, o[j][3] * i1);
    }
}

extern "C" void kernel_launch(void* const* d_in, const int* in_sizes, int n_in,
                              void* d_out, int out_size)
{
    const float* Q  = (const float*)d_in[0];
    const float* K  = (const float*)d_in[1];
    const float* V  = (const float*)d_in[2];
    const float* Wq = (const float*)d_in[3];
    const float* bq = (const float*)d_in[4];
    const float* Wk = (const float*)d_in[5];
    const float* bk = (const float*)d_in[6];
    const float* Wv = (const float*)d_in[7];
    const float* bv = (const float*)d_in[8];
    const float* Wo = (const float*)d_in[9];
    const float* bo = (const float*)d_in[10];
    float* out = (float*)d_out;

    float *gq, *gk, *gv, *gcat;
    cudaGetSymbolAddress((void**)&gq, g_q);
    cudaGetSymbolAddress((void**)&gk, g_k);
    cudaGetSymbolAddress((void**)&gv, g_v);
    cudaGetSymbolAddress((void**)&gcat, g_cat);

    const int proj_smem  = (NSTAGE * A_STAGE_WORDS + NSTAGE * B0_STAGE_WORDS) * 4; // 75776
    const int outg_smem  = (NSTAGE * A_STAGE_WORDS + NSTAGE * B1_STAGE_WORDS) * 4; // 81920
    const int flash_smem = (2 * KB_WORDS + 2 * VB_WORDS + P_WORDS) * 4;            // 106496

    cudaFuncSetAttribute(proj_gemm3_v3_kernel,
                         cudaFuncAttributeMaxDynamicSharedMemorySize, proj_smem);
    cudaFuncSetAttribute(gemm_v3_kernel<1>,
                         cudaFuncAttributeMaxDynamicSharedMemorySize, outg_smem);
    cudaFuncSetAttribute(flash_mma_kernel,
                         cudaFuncAttributeMaxDynamicSharedMemorySize, flash_smem);

    ProjArgs pa;
    pa.X[0] = Q;  pa.X[1] = K;  pa.X[2] = V;
    pa.W[0] = Wq; pa.W[1] = Wk; pa.W[2] = Wv;
    pa.bias[0] = bq; pa.bias[1] = bk; pa.bias[2] = bv;
    pa.out[0] = gq; pa.out[1] = gk; pa.out[2] = gv;

    dim3 pgrd(D_MODEL / 128, M_TOTAL / 128, 3);
    proj_gemm3_v3_kernel<<<pgrd, dim3(256), proj_smem>>>(pa);

    dim3 fgrd(SEQ / 128, BATCH * NUM_HEADS);
    flash_mma_kernel<<<fgrd, dim3(256), flash_smem>>>();

    dim3 ogrd(D_MODEL / 128, M_TOTAL / 128);
    gemm_v3_kernel<1><<<ogrd, dim3(256), outg_smem>>>(gcat, Wo, bo, out);
}

// round 9
// speedup vs baseline: 1.4022x; 1.0787x over previous
#include <cuda_runtime.h>
#include <math.h>
#include <stdint.h>

#define D_MODEL 1024
#define NUM_HEADS 16
#define DK 64
#define BATCH 2
#define SEQ 2048
#define M_TOTAL (BATCH * SEQ)  // 4096

// GEMM smem geometry (4-stage cp.async)
#define A_ROW_STRIDE 20
#define A_STAGE_WORDS (128 * A_ROW_STRIDE)
#define B0_STAGE_WORDS (16 * 136)
#define B1_STAGE_WORDS (128 * A_ROW_STRIDE)
#define NSTAGE 4

// flash smem strides (bank-tuned): K loads use gid*stride+tig -> stride%32==4;
// V loads use tig*stride+gid -> stride%32==8. K/V double-buffered (cp.async).
#define KRS 68
#define VRS 72
#define KB_WORDS (64 * KRS)     // 4352 per buffer
#define VB_WORDS (64 * VRS)     // 4608 per buffer

__device__ float g_q[BATCH * NUM_HEADS * SEQ * DK];
__device__ float g_k[BATCH * NUM_HEADS * SEQ * DK];
__device__ float g_v[BATCH * NUM_HEADS * SEQ * DK];
__device__ float g_cat[M_TOTAL * D_MODEL];

__device__ __forceinline__ uint32_t f2tf(float f) {
    uint32_t u;
    asm("cvt.rna.tf32.f32 %0, %1;" : "=r"(u) : "f"(f));
    return u;
}

__device__ __forceinline__ void mma_tf32(float* c, const uint32_t* a, const uint32_t* b) {
    asm volatile(
        "mma.sync.aligned.m16n8k8.row.col.f32.tf32.tf32.f32 "
        "{%0,%1,%2,%3}, {%4,%5,%6,%7}, {%8,%9}, {%0,%1,%2,%3};"
        : "+f"(c[0]), "+f"(c[1]), "+f"(c[2]), "+f"(c[3])
        : "r"(a[0]), "r"(a[1]), "r"(a[2]), "r"(a[3]), "r"(b[0]), "r"(b[1]));
}

__device__ __forceinline__ void cpa16(uint32_t* smem_dst, const float* gsrc) {
    uint32_t s = (uint32_t)__cvta_generic_to_shared(smem_dst);
    asm volatile("cp.async.cg.shared.global [%0], [%1], 16;" :: "r"(s), "l"(gsrc));
}
__device__ __forceinline__ void cpa_commit() {
    asm volatile("cp.async.commit_group;");
}
template <int N>
__device__ __forceinline__ void cpa_wait() {
    asm volatile("cp.async.wait_group %0;" :: "n"(N));
}

// =====================================================================
// TF32 GEMM (R7/R8, known-good): cp.async 4-stage, ONE sync per k-chunk.
// =====================================================================
template <int MODE>
__global__ __launch_bounds__(256, 2) void gemm_v3_kernel(
    const float* __restrict__ X, const float* __restrict__ W,
    const float* __restrict__ bias, float* __restrict__ out)
{
    extern __shared__ uint32_t sg[];
    uint32_t* smA = sg;
    uint32_t* smB = sg + NSTAGE * A_STAGE_WORDS;
    const int BSTW = (MODE == 0) ? B0_STAGE_WORDS : B1_STAGE_WORDS;

    const int t    = threadIdx.x;
    const int n0   = blockIdx.x * 128;
    const int m0   = blockIdx.y * 128;
    const int warp = t >> 5;
    const int lane = t & 31;
    const int gid  = lane >> 2;
    const int tig  = lane & 3;
    const int wm   = (warp & 1) * 64;
    const int wn   = (warp >> 1) * 32;

    const int am[2] = { (t + 0) >> 2, (t + 256) >> 2 };
    const int ak4   = (t & 3) << 2;

    float acc[4][4][4];
#pragma unroll
    for (int i = 0; i < 4; i++)
#pragma unroll
        for (int j = 0; j < 4; j++)
#pragma unroll
            for (int k = 0; k < 4; k++) acc[i][j][k] = 0.f;

    auto issue = [&](int stage, int kc) {
        uint32_t* As_ = smA + stage * A_STAGE_WORDS;
        uint32_t* Bs_ = smB + stage * BSTW;
#pragma unroll
        for (int rep = 0; rep < 2; rep++) {
            int m = am[rep];
            cpa16(As_ + m * A_ROW_STRIDE + ak4,
                  X + (size_t)(m0 + m) * D_MODEL + kc * 16 + ak4);
        }
#pragma unroll
        for (int rep = 0; rep < 2; rep++) {
            int f = t + rep * 256;
            if (MODE == 0) {
                int k = f >> 5, n4 = (f & 31) << 2;
                int bn = n0 + n4;
                int ck = ((k >> 2) & 3) << 2;
                cpa16(Bs_ + k * 136 + (n4 ^ ck),
                      W + (size_t)(bn >> 6) * (D_MODEL * DK)
                        + (size_t)(kc * 16 + k) * DK + (bn & 63));
            } else {
                int n = f >> 2, k4 = (f & 3) << 2;
                cpa16(Bs_ + n * A_ROW_STRIDE + k4,
                      W + (size_t)(n0 + n) * D_MODEL + kc * 16 + k4);
            }
        }
    };

    auto compute = [&](int stage) {
        uint32_t* As_ = smA + stage * A_STAGE_WORDS;
        uint32_t* Bs_ = smB + stage * BSTW;
#pragma unroll
        for (int ks = 0; ks < 2; ks++) {
            const int kb = ks * 8;
            uint32_t af[4][4];
#pragma unroll
            for (int mt = 0; mt < 4; mt++) {
                const int r = (wm + mt * 16 + gid) * A_ROW_STRIDE;
                af[mt][0] = As_[r + kb + tig];
                af[mt][1] = As_[r + 8 * A_ROW_STRIDE + kb + tig];
                af[mt][2] = As_[r + kb + tig + 4];
                af[mt][3] = As_[r + 8 * A_ROW_STRIDE + kb + tig + 4];
            }
            uint32_t bf[4][2];
#pragma unroll
            for (int nt = 0; nt < 4; nt++) {
                const int ncol = wn + nt * 8 + gid;
                if (MODE == 0) {
                    const int x0 = ks ? 8 : 0;
                    const int x1 = ks ? 12 : 4;
                    bf[nt][0] = Bs_[(kb + tig) * 136 + (ncol ^ x0)];
                    bf[nt][1] = Bs_[(kb + tig + 4) * 136 + (ncol ^ x1)];
                } else {
                    bf[nt][0] = Bs_[ncol * A_ROW_STRIDE + kb + tig];
                    bf[nt][1] = Bs_[ncol * A_ROW_STRIDE + kb + tig + 4];
                }
            }
#pragma unroll
            for (int mt = 0; mt < 4; mt++)
#pragma unroll
                for (int nt = 0; nt < 4; nt++) mma_tf32(acc[mt][nt], af[mt], bf[nt]);
        }
    };

    issue(0, 0); cpa_commit();
    issue(1, 1); cpa_commit();
    issue(2, 2); cpa_commit();
    for (int kc = 0; kc < 64; kc++) {
        cpa_wait<2>();
        __syncthreads();
        compute(kc & 3);
        if (kc + 3 < 64) issue((kc + 3) & 3, kc + 3);
        cpa_commit();
    }

#pragma unroll
    for (int mt = 0; mt < 4; mt++) {
#pragma unroll
        for (int nt = 0; nt < 4; nt++) {
            const int r0 = m0 + wm + mt * 16 + gid;
            const int r1 = r0 + 8;
            const int c  = n0 + wn + nt * 8 + tig * 2;
            const float bv0 = bias[c], bv1 = bias[c + 1];
            float2 v0 = make_float2(acc[mt][nt][0] + bv0, acc[mt][nt][1] + bv1);
            float2 v1 = make_float2(acc[mt][nt][2] + bv0, acc[mt][nt][3] + bv1);
            if (MODE == 0) {
                const int h = c >> 6, kd = c & 63;
                const int b0_ = r0 >> 11, s0 = r0 & 2047;
                const int b1_ = r1 >> 11, s1 = r1 & 2047;
                *(float2*)(out + (((size_t)b0_ * NUM_HEADS + h) * SEQ + s0) * DK + kd) = v0;
                *(float2*)(out + (((size_t)b1_ * NUM_HEADS + h) * SEQ + s1) * DK + kd) = v1;
            } else {
                *(float2*)(out + (size_t)r0 * D_MODEL + c) = v0;
                *(float2*)(out + (size_t)r1 * D_MODEL + c) = v1;
            }
        }
    }
}

// proj wrapper (R7/R8, known-good): grid.z selects Q/K/V
struct ProjArgs {
    const float* X[3];
    const float* W[3];
    const float* bias[3];
    float* out[3];
};

__global__ __launch_bounds__(256, 2) void proj_gemm3_v3_kernel(ProjArgs args)
{
    extern __shared__ uint32_t sg[];
    const int z = blockIdx.z;
    const float* X    = args.X[z];
    const float* W    = args.W[z];
    const float* bias = args.bias[z];
    float* out        = args.out[z];

    uint32_t* smA = sg;
    uint32_t* smB = sg + NSTAGE * A_STAGE_WORDS;

    const int t    = threadIdx.x;
    const int n0   = blockIdx.x * 128;
    const int m0   = blockIdx.y * 128;
    const int warp = t >> 5;
    const int lane = t & 31;
    const int gid  = lane >> 2;
    const int tig  = lane & 3;
    const int wm   = (warp & 1) * 64;
    const int wn   = (warp >> 1) * 32;

    const int am[2] = { (t + 0) >> 2, (t + 256) >> 2 };
    const int ak4   = (t & 3) << 2;

    float acc[4][4][4];
#pragma unroll
    for (int i = 0; i < 4; i++)
#pragma unroll
        for (int j = 0; j < 4; j++)
#pragma unroll
            for (int k = 0; k < 4; k++) acc[i][j][k] = 0.f;

    auto issue = [&](int stage, int kc) {
        uint32_t* As_ = smA + stage * A_STAGE_WORDS;
        uint32_t* Bs_ = smB + stage * B0_STAGE_WORDS;
#pragma unroll
        for (int rep = 0; rep < 2; rep++) {
            int m = am[rep];
            cpa16(As_ + m * A_ROW_STRIDE + ak4,
                  X + (size_t)(m0 + m) * D_MODEL + kc * 16 + ak4);
        }
#pragma unroll
        for (int rep = 0; rep < 2; rep++) {
            int f = t + rep * 256;
            int k = f >> 5, n4 = (f & 31) << 2;
            int bn = n0 + n4;
            int ck = ((k >> 2) & 3) << 2;
            cpa16(Bs_ + k * 136 + (n4 ^ ck),
                  W + (size_t)(bn >> 6) * (D_MODEL * DK)
                    + (size_t)(kc * 16 + k) * DK + (bn & 63));
        }
    };

    auto compute = [&](int stage) {
        uint32_t* As_ = smA + stage * A_STAGE_WORDS;
        uint32_t* Bs_ = smB + stage * B0_STAGE_WORDS;
#pragma unroll
        for (int ks = 0; ks < 2; ks++) {
            const int kb = ks * 8;
            const int x0 = ks ? 8 : 0;
            const int x1 = ks ? 12 : 4;
            uint32_t af[4][4];
#pragma unroll
            for (int mt = 0; mt < 4; mt++) {
                const int r = (wm + mt * 16 + gid) * A_ROW_STRIDE;
                af[mt][0] = As_[r + kb + tig];
                af[mt][1] = As_[r + 8 * A_ROW_STRIDE + kb + tig];
                af[mt][2] = As_[r + kb + tig + 4];
                af[mt][3] = As_[r + 8 * A_ROW_STRIDE + kb + tig + 4];
            }
            uint32_t bf[4][2];
#pragma unroll
            for (int nt = 0; nt < 4; nt++) {
                const int ncol = wn + nt * 8 + gid;
                bf[nt][0] = Bs_[(kb + tig) * 136 + (ncol ^ x0)];
                bf[nt][1] = Bs_[(kb + tig + 4) * 136 + (ncol ^ x1)];
            }
#pragma unroll
            for (int mt = 0; mt < 4; mt++)
#pragma unroll
                for (int nt = 0; nt < 4; nt++) mma_tf32(acc[mt][nt], af[mt], bf[nt]);
        }
    };

    issue(0, 0); cpa_commit();
    issue(1, 1); cpa_commit();
    issue(2, 2); cpa_commit();
    for (int kc = 0; kc < 64; kc++) {
        cpa_wait<2>();
        __syncthreads();
        compute(kc & 3);
        if (kc + 3 < 64) issue((kc + 3) & 3, kc + 3);
        cpa_commit();
    }

#pragma unroll
    for (int mt = 0; mt < 4; mt++) {
#pragma unroll
        for (int nt = 0; nt < 4; nt++) {
            const int r0 = m0 + wm + mt * 16 + gid;
            const int r1 = r0 + 8;
            const int c  = n0 + wn + nt * 8 + tig * 2;
            const float bv0 = bias[c], bv1 = bias[c + 1];
            float2 v0 = make_float2(acc[mt][nt][0] + bv0, acc[mt][nt][1] + bv1);
            float2 v1 = make_float2(acc[mt][nt][2] + bv0, acc[mt][nt][3] + bv1);
            const int h = c >> 6, kd = c & 63;
            const int b0_ = r0 >> 11, s0 = r0 & 2047;
            const int b1_ = r1 >> 11, s1 = r1 & 2047;
            *(float2*)(out + (((size_t)b0_ * NUM_HEADS + h) * SEQ + s0) * DK + kd) = v0;
            *(float2*)(out + (((size_t)b1_ * NUM_HEADS + h) * SEQ + s1) * DK + kd) = v1;
        }
    }
}

// =====================================================================
// Flash attention v7: register-resident P via K-row permutation.
// K rows stored at permuted position n(kv) = 2(kv&3)+(kv>>2) within each
// 8-group, so the S-mma C-fragment IS the PV A-fragment ({e0,e2,e1,e3}).
// No P smem, no syncwarps. cp.async double-buffered K/V.
// =====================================================================
__global__ __launch_bounds__(256, 2) void flash_mma_kernel()
{
    extern __shared__ uint32_t smu[];
    uint32_t* KsB = smu;                  // 2 x [64][KRS] (rows permuted)
    uint32_t* VsB = smu + 2 * KB_WORDS;   // 2 x [64][VRS] (rows natural)

    const int t    = threadIdx.x;
    const int warp = t >> 5;
    const int lane = t & 31;
    const int gid  = lane >> 2;
    const int tig  = lane & 3;
    const int q0   = blockIdx.x * 128;
    const int bh   = blockIdx.y;

    const float* qb = g_q + (size_t)bh * SEQ * DK;
    const float* kb = g_k + (size_t)bh * SEQ * DK;
    const float* vb = g_v + (size_t)bh * SEQ * DK;

    const int r0 = q0 + warp * 16 + gid;
    const int r1 = r0 + 8;
    uint32_t qf[8][4];
#pragma unroll
    for (int kk = 0; kk < 8; kk++) {
        qf[kk][0] = f2tf(qb[(size_t)r0 * DK + kk * 8 + tig]     * 0.125f);
        qf[kk][1] = f2tf(qb[(size_t)r1 * DK + kk * 8 + tig]     * 0.125f);
        qf[kk][2] = f2tf(qb[(size_t)r0 * DK + kk * 8 + tig + 4] * 0.125f);
        qf[kk][3] = f2tf(qb[(size_t)r1 * DK + kk * 8 + tig + 4] * 0.125f);
    }

    float m0 = -INFINITY, m1 = -INFINITY, l0 = 0.f, l1 = 0.f;
    float o[8][4];
#pragma unroll
    for (int j = 0; j < 8; j++)
#pragma unroll
        for (int k = 0; k < 4; k++) o[j][k] = 0.f;

    // per-thread copy coords: 4 chunks of 16B per matrix per tile
    const int crow[4] = { (t + 0) >> 4, (t + 256) >> 4, (t + 512) >> 4, (t + 768) >> 4 };
    const int cc4     = (t & 15) << 2;

    auto issue_kv = [&](int buf, int s0) {
        uint32_t* Ks_ = KsB + buf * KB_WORDS;
        uint32_t* Vs_ = VsB + buf * VB_WORDS;
#pragma unroll
        for (int rep = 0; rep < 4; rep++) {
            int row  = crow[rep];
            int prow = (row & ~7) | ((row & 3) << 1) | ((row >> 2) & 1);
            cpa16(Ks_ + prow * KRS + cc4, kb + (size_t)(s0 + row) * DK + cc4);
            cpa16(Vs_ + row  * VRS + cc4, vb + (size_t)(s0 + row) * DK + cc4);
        }
        cpa_commit();
    };

    issue_kv(0, 0);

    for (int tile = 0; tile < SEQ / 64; tile++) {
        const int buf = tile & 1;
        uint32_t* Ks = KsB + buf * KB_WORDS;
        uint32_t* Vs = VsB + buf * VB_WORDS;

        cpa_wait<0>();
        __syncthreads();
        if (tile + 1 < SEQ / 64) issue_kv(buf ^ 1, (tile + 1) * 64);

        // ---- S = Q K^T (K rows permuted -> C-frag in A-frag order) ----
        float sacc[8][4];
#pragma unroll
        for (int j = 0; j < 8; j++)
#pragma unroll
            for (int k = 0; k < 4; k++) sacc[j][k] = 0.f;
#pragma unroll
        for (int kk = 0; kk < 8; kk++) {
            uint32_t bf[8][2];
#pragma unroll
            for (int j = 0; j < 8; j++) {
                bf[j][0] = Ks[(j * 8 + gid) * KRS + kk * 8 + tig];
                bf[j][1] = Ks[(j * 8 + gid) * KRS + kk * 8 + tig + 4];
            }
#pragma unroll
            for (int j = 0; j < 8; j++) mma_tf32(sacc[j], qf[kk], bf[j]);
        }

        // ---- fragment-resident online softmax ----
        float t0 = -INFINITY, t1 = -INFINITY;
#pragma unroll
        for (int j = 0; j < 8; j++) {
            t0 = fmaxf(t0, fmaxf(sacc[j][0], sacc[j][1]));
            t1 = fmaxf(t1, fmaxf(sacc[j][2], sacc[j][3]));
        }
        t0 = fmaxf(t0, __shfl_xor_sync(0xffffffffu, t0, 1));
        t0 = fmaxf(t0, __shfl_xor_sync(0xffffffffu, t0, 2));
        t1 = fmaxf(t1, __shfl_xor_sync(0xffffffffu, t1, 1));
        t1 = fmaxf(t1, __shfl_xor_sync(0xffffffffu, t1, 2));

        float nm0 = fmaxf(m0, t0), nm1 = fmaxf(m1, t1);
        float a0 = __expf(m0 - nm0), a1 = __expf(m1 - nm1);
        m0 = nm0; m1 = nm1;

        float p0 = 0.f, p1 = 0.f;
#pragma unroll
        for (int j = 0; j < 8; j++) {
            float e0 = __expf(sacc[j][0] - nm0);
            float e1 = __expf(sacc[j][1] - nm0);
            float e2 = __expf(sacc[j][2] - nm1);
            float e3 = __expf(sacc[j][3] - nm1);
            p0 += e0 + e1;
            p1 += e2 + e3;
            // keep P in registers, rna-rounded to tf32 (A-frag order e0,e2,e1,e3 used below)
            sacc[j][0] = __uint_as_float(f2tf(e0));
            sacc[j][1] = __uint_as_float(f2tf(e1));
            sacc[j][2] = __uint_as_float(f2tf(e2));
            sacc[j][3] = __uint_as_float(f2tf(e3));
        }
        p0 += __shfl_xor_sync(0xffffffffu, p0, 1);
        p0 += __shfl_xor_sync(0xffffffffu, p0, 2);
        p1 += __shfl_xor_sync(0xffffffffu, p1, 1);
        p1 += __shfl_xor_sync(0xffffffffu, p1, 2);
        l0 = l0 * a0 + p0;
        l1 = l1 * a1 + p1;

#pragma unroll
        for (int j = 0; j < 8; j++) {
            o[j][0] *= a0; o[j][1] *= a0;
            o[j][2] *= a1; o[j][3] *= a1;
        }

        // ---- O += P V (P = sacc registers, kk-th S j-tile is PV k-group) ----
#pragma unroll
        for (int kk = 0; kk < 8; kk++) {
            uint32_t af[4];
            af[0] = __float_as_uint(sacc[kk][0]);
            af[1] = __float_as_uint(sacc[kk][2]);
            af[2] = __float_as_uint(sacc[kk][1]);
            af[3] = __float_as_uint(sacc[kk][3]);
#pragma unroll
            for (int j = 0; j < 8; j++) {
                uint32_t bf[2];
                bf[0] = Vs[(kk * 8 + tig) * VRS + j * 8 + gid];
                bf[1] = Vs[(kk * 8 + tig + 4) * VRS + j * 8 + gid];
                mma_tf32(o[j], af, bf);
            }
        }
    }

    const float i0 = 1.f / l0, i1 = 1.f / l1;
    const int b_ = bh >> 4, h = bh & 15;
    float* row0 = g_cat + (size_t)(b_ * SEQ + r0) * D_MODEL + h * DK;
    float* row1 = g_cat + (size_t)(b_ * SEQ + r1) * D_MODEL + h * DK;
#pragma unroll
    for (int j = 0; j < 8; j++) {
        *(float2*)(row0 + j * 8 + tig * 2) = make_float2(o[j][0] * i0, o[j][1] * i0);
        *(float2*)(row1 + j * 8 + tig * 2) = make_float2(o[j][2] * i1, o[j][3] * i1);
    }
}

extern "C" void kernel_launch(void* const* d_in, const int* in_sizes, int n_in,
                              void* d_out, int out_size)
{
    const float* Q  = (const float*)d_in[0];
    const float* K  = (const float*)d_in[1];
    const float* V  = (const float*)d_in[2];
    const float* Wq = (const float*)d_in[3];
    const float* bq = (const float*)d_in[4];
    const float* Wk = (const float*)d_in[5];
    const float* bk = (const float*)d_in[6];
    const float* Wv = (const float*)d_in[7];
    const float* bv = (const float*)d_in[8];
    const float* Wo = (const float*)d_in[9];
    const float* bo = (const float*)d_in[10];
    float* out = (float*)d_out;

    float *gq, *gk, *gv, *gcat;
    cudaGetSymbolAddress((void**)&gq, g_q);
    cudaGetSymbolAddress((void**)&gk, g_k);
    cudaGetSymbolAddress((void**)&gv, g_v);
    cudaGetSymbolAddress((void**)&gcat, g_cat);

    const int proj_smem  = (NSTAGE * A_STAGE_WORDS + NSTAGE * B0_STAGE_WORDS) * 4; // 75776
    const int outg_smem  = (NSTAGE * A_STAGE_WORDS + NSTAGE * B1_STAGE_WORDS) * 4; // 81920
    const int flash_smem = (2 * KB_WORDS + 2 * VB_WORDS) * 4;                      // 71680

    cudaFuncSetAttribute(proj_gemm3_v3_kernel,
                         cudaFuncAttributeMaxDynamicSharedMemorySize, proj_smem);
    cudaFuncSetAttribute(gemm_v3_kernel<1>,
                         cudaFuncAttributeMaxDynamicSharedMemorySize, outg_smem);
    cudaFuncSetAttribute(flash_mma_kernel,
                         cudaFuncAttributeMaxDynamicSharedMemorySize, flash_smem);

    ProjArgs pa;
    pa.X[0] = Q;  pa.X[1] = K;  pa.X[2] = V;
    pa.W[0] = Wq; pa.W[1] = Wk; pa.W[2] = Wv;
    pa.bias[0] = bq; pa.bias[1] = bk; pa.bias[2] = bv;
    pa.out[0] = gq; pa.out[1] = gk; pa.out[2] = gv;

    dim3 pgrd(D_MODEL / 128, M_TOTAL / 128, 3);
    proj_gemm3_v3_kernel<<<pgrd, dim3(256), proj_smem>>>(pa);

    dim3 fgrd(SEQ / 128, BATCH * NUM_HEADS);
    flash_mma_kernel<<<fgrd, dim3(256), flash_smem>>>();

    dim3 ogrd(D_MODEL / 128, M_TOTAL / 128);
    gemm_v3_kernel<1><<<ogrd, dim3(256), outg_smem>>>(gcat, Wo, bo, out);
}